// round 2
// baseline (speedup 1.0000x reference)
#include <cuda_runtime.h>
#include <math.h>

#define NN 100000
#define EE 1600000
#define MM (EE + NN)
#define NB 49            // ceil(NN / 2048)
#define EPSV 1e-5f

// ---------------- scratch (static device allocations; no cudaMalloc) ----------------
__device__ int   g_is64;
__device__ int   g_deg[NN];
__device__ float g_dinv[NN];
__device__ int   g_start[NN];
__device__ int   g_cursor[NN];
__device__ int   g_tilesum[NB];
__device__ int   g_tileoff[NB];
__device__ int2  g_cw[MM];          // (src, norm-bits) per CSR slot
__device__ float g_s[NN];           // row sums of normalized adjacency
__device__ float g_h[NN * 64];      // GEMM output
__device__ float g_agg[NN * 64];    // aggregation output
__device__ float g_stats1[128];     // [sum(64), sumsq(64)]
__device__ float g_stats2[128];
__device__ float g_W2f[64 * 64];    // BN1-folded W2
__device__ float g_W3f[64 * 40];    // BN2-folded W3
__device__ float g_t2[64];
__device__ float g_t3[64];
__device__ float g_zero64[64];

// ---------------- graph build ----------------
__global__ void k_init() {
    int i = blockIdx.x * blockDim.x + threadIdx.x;
    if (i < NN) g_deg[i] = 1;                 // self-loop
    if (i < 128) { g_stats1[i] = 0.f; g_stats2[i] = 0.f; }
    if (i < 64) g_zero64[i] = 0.f;
    if (i == 0) g_is64 = 1;
}

// If edge_index is really int64, the first EE int64 entries are edge_index[0]
// (all in [0, NN)). If it's int32, reading the buffer as int64 mixes adjacent
// indices into huge values -> flag flips to 0. Reads only min(buffer) bytes.
__global__ void k_detect(const long long* __restrict__ p) {
    int i = blockIdx.x * blockDim.x + threadIdx.x;
    if (i < EE) {
        long long v = p[i];
        if (v < 0 || v >= NN) g_is64 = 0;   // benign race: all writers store 0
    }
}

__device__ __forceinline__ long long edge_at(const void* ei, int idx) {
    if (g_is64) return ((const long long*)ei)[idx];
    return (long long)((const int*)ei)[idx];
}

__global__ void k_degree(const void* __restrict__ ei) {
    int i = blockIdx.x * blockDim.x + threadIdx.x;
    if (i >= EE) return;
    long long d = edge_at(ei, EE + i);
    if ((unsigned long long)d < (unsigned long long)NN)
        atomicAdd(&g_deg[(int)d], 1);
}

__global__ void k_dinv() {
    int i = blockIdx.x * blockDim.x + threadIdx.x;
    if (i < NN) g_dinv[i] = rsqrtf((float)g_deg[i]);
}

__global__ void k_scanA() {   // block-tile sums (tile = 2048)
    int base = blockIdx.x * 2048;
    int s = 0;
    for (int i = threadIdx.x; i < 2048; i += 256) {
        int idx = base + i;
        if (idx < NN) s += g_deg[idx];
    }
    __shared__ int sh[256];
    sh[threadIdx.x] = s;
    __syncthreads();
    for (int o = 128; o > 0; o >>= 1) {
        if (threadIdx.x < o) sh[threadIdx.x] += sh[threadIdx.x + o];
        __syncthreads();
    }
    if (threadIdx.x == 0) g_tilesum[blockIdx.x] = sh[0];
}

__global__ void k_scanB() {   // exclusive scan of NB tile sums
    if (threadIdx.x == 0) {
        int a = 0;
        for (int b = 0; b < NB; b++) { g_tileoff[b] = a; a += g_tilesum[b]; }
    }
}

__global__ void k_scanC() {   // intra-tile exclusive scan -> start/cursor
    int tid = threadIdx.x;
    int base = blockIdx.x * 2048 + tid * 8;
    int loc[8];
    int s = 0;
    #pragma unroll
    for (int j = 0; j < 8; j++) {
        int idx = base + j;
        int d = (idx < NN) ? g_deg[idx] : 0;
        loc[j] = s; s += d;
    }
    __shared__ int sh[256];
    sh[tid] = s;
    __syncthreads();
    int run = s;
    for (int o = 1; o < 256; o <<= 1) {
        int v = (tid >= o) ? sh[tid - o] : 0;
        __syncthreads();
        sh[tid] += v;
        __syncthreads();
    }
    int off = g_tileoff[blockIdx.x] + sh[tid] - run;
    #pragma unroll
    for (int j = 0; j < 8; j++) {
        int idx = base + j;
        if (idx < NN) { int p = off + loc[j]; g_start[idx] = p; g_cursor[idx] = p; }
    }
}

__global__ void k_fill(const void* __restrict__ ei) {
    int i = blockIdx.x * blockDim.x + threadIdx.x;
    if (i >= MM) return;
    int s, d;
    if (i < EE) {
        long long ls = edge_at(ei, i);
        long long ld = edge_at(ei, EE + i);
        if ((unsigned long long)ls >= (unsigned long long)NN) return;
        if ((unsigned long long)ld >= (unsigned long long)NN) return;
        s = (int)ls; d = (int)ld;
    } else {
        s = i - EE; d = s;
    }
    float w = g_dinv[s] * g_dinv[d];
    int pos = atomicAdd(&g_cursor[d], 1);
    g_cw[pos] = make_int2(s, __float_as_int(w));
}

__global__ void k_rowsum() {  // s_d = sum of norms per dst node
    int wid  = (blockIdx.x * blockDim.x + threadIdx.x) >> 5;
    int lane = threadIdx.x & 31;
    if (wid >= NN) return;
    int st = g_start[wid], en = st + g_deg[wid];
    float s = 0.f;
    for (int e = st + lane; e < en; e += 32) s += __int_as_float(g_cw[e].y);
    #pragma unroll
    for (int o = 16; o > 0; o >>= 1) s += __shfl_xor_sync(0xffffffffu, s, o);
    if (lane == 0) g_s[wid] = s;
}

// ---------------- GEMM: out[N x NC] = in[N x 64] @ W[64 x NC] ----------------
// blockDim must be (NC/4)*16; block tile = 64 rows x NC cols.
template <int NC>
__global__ void k_gemm(const float* __restrict__ in, const float* __restrict__ W,
                       float* __restrict__ out) {
    __shared__ float XsT[64 * 68];   // [k][row], padded
    __shared__ float Ws[64 * NC];    // [k][j]
    const int nth = (NC / 4) * 16;
    int tid = threadIdx.x;
    int row0 = blockIdx.x * 64;

    for (int i = tid; i < 64 * NC / 4; i += nth)
        ((float4*)Ws)[i] = ((const float4*)W)[i];

    for (int i = tid; i < 64 * 16; i += nth) {
        int r = i & 63, k4 = i >> 6;
        int gr = row0 + r;
        float4 v = make_float4(0.f, 0.f, 0.f, 0.f);
        if (gr < NN) v = ((const float4*)(in + (size_t)gr * 64))[k4];
        XsT[(k4 * 4 + 0) * 68 + r] = v.x;
        XsT[(k4 * 4 + 1) * 68 + r] = v.y;
        XsT[(k4 * 4 + 2) * 68 + r] = v.z;
        XsT[(k4 * 4 + 3) * 68 + r] = v.w;
    }
    __syncthreads();

    int tc = tid % (NC / 4), tr = tid / (NC / 4);
    int c0 = tc * 4, r0 = tr * 4;
    float acc[4][4];
    #pragma unroll
    for (int i = 0; i < 4; i++)
        #pragma unroll
        for (int j = 0; j < 4; j++) acc[i][j] = 0.f;

    #pragma unroll 8
    for (int k = 0; k < 64; k++) {
        float4 b = *(const float4*)&Ws[k * NC + c0];
        float4 a = *(const float4*)&XsT[k * 68 + r0];
        acc[0][0] += a.x * b.x; acc[0][1] += a.x * b.y; acc[0][2] += a.x * b.z; acc[0][3] += a.x * b.w;
        acc[1][0] += a.y * b.x; acc[1][1] += a.y * b.y; acc[1][2] += a.y * b.z; acc[1][3] += a.y * b.w;
        acc[2][0] += a.z * b.x; acc[2][1] += a.z * b.y; acc[2][2] += a.z * b.z; acc[2][3] += a.z * b.w;
        acc[3][0] += a.w * b.x; acc[3][1] += a.w * b.y; acc[3][2] += a.w * b.z; acc[3][3] += a.w * b.w;
    }

    #pragma unroll
    for (int i = 0; i < 4; i++) {
        int gr = row0 + r0 + i;
        if (gr < NN)
            *(float4*)&out[(size_t)gr * NC + c0] =
                make_float4(acc[i][0], acc[i][1], acc[i][2], acc[i][3]);
    }
}

// ---------------- aggregation: one warp per dst node, no atomics ----------------
template <int NC>
__global__ void k_agg(const float* __restrict__ h, const float* __restrict__ bias,
                      const float* __restrict__ t, float* __restrict__ out) {
    int wid  = (blockIdx.x * blockDim.x + threadIdx.x) >> 5;
    int lane = threadIdx.x & 31;
    if (wid >= NN) return;
    int e = g_start[wid], en = e + g_deg[wid];
    float acc0 = 0.f, acc1 = 0.f;
    int2 cw = __ldg(&g_cw[e]);       // deg >= 1 (self-loop) always
    while (1) {
        int s = cw.x;
        float w = __int_as_float(cw.y);
        ++e;
        bool more = (e < en);
        if (more) cw = __ldg(&g_cw[e]);   // prefetch next edge
        const float* hp = h + (size_t)s * NC;
        acc0 += w * __ldg(hp + lane);
        if (NC > 32 && lane + 32 < NC) acc1 += w * __ldg(hp + lane + 32);
        if (!more) break;
    }
    float sd = g_s[wid];
    out[(size_t)wid * NC + lane] = acc0 + bias[lane] + sd * t[lane];
    if (NC > 32 && lane + 32 < NC)
        out[(size_t)wid * NC + lane + 32] = acc1 + bias[lane + 32] + sd * t[lane + 32];
}

// ---------------- BN column stats (sum, sumsq) ----------------
__global__ void k_stats(const float* __restrict__ a, float* __restrict__ st) {
    int col = threadIdx.x & 63, sub = threadIdx.x >> 6;
    float s = 0.f, q = 0.f;
    for (int r = blockIdx.x * 4 + sub; r < NN; r += gridDim.x * 4) {
        float v = a[(size_t)r * 64 + col];
        s += v; q += v * v;
    }
    __shared__ float shs[256], shq[256];
    shs[threadIdx.x] = s; shq[threadIdx.x] = q;
    __syncthreads();
    if (sub == 0) {
        s = shs[col] + shs[col + 64] + shs[col + 128] + shs[col + 192];
        q = shq[col] + shq[col + 64] + shq[col + 128] + shq[col + 192];
        atomicAdd(&st[col], s);
        atomicAdd(&st[col + 64], q);
    }
}

// ---------------- fold BN into next layer's weights ----------------
// bn(x)[k] = x*a[k] + c[k];  (bn(h))@W = h@(a (.) W) + c^T W
// t[j] = c^T W passes through propagation scaled by s_d (handled in k_agg).
template <int NCN>
__global__ void k_fold(const float* __restrict__ W, const float* __restrict__ g,
                       const float* __restrict__ be, const float* __restrict__ st,
                       float* __restrict__ Wf, float* __restrict__ t) {
    __shared__ float a[64], c[64];
    int tid = threadIdx.x;
    if (tid < 64) {
        float mean = st[tid] * (1.f / NN);
        float var  = st[tid + 64] * (1.f / NN) - mean * mean;
        float ai = g[tid] * rsqrtf(var + EPSV);
        a[tid] = ai;
        c[tid] = be[tid] - mean * ai;
    }
    __syncthreads();
    for (int i = tid; i < 64 * NCN; i += 256) Wf[i] = a[i / NCN] * W[i];
    if (tid < NCN) {
        float tv = 0.f;
        #pragma unroll
        for (int k = 0; k < 64; k++) tv += c[k] * W[k * NCN + tid];
        t[tid] = tv;
    }
}

// ---------------- log_softmax over 40 cols, one warp per row ----------------
__global__ void k_lsm(const float* __restrict__ emb, float* __restrict__ out) {
    int wid  = (blockIdx.x * blockDim.x + threadIdx.x) >> 5;
    int lane = threadIdx.x & 31;
    if (wid >= NN) return;
    const float* e = emb + (size_t)wid * 40;
    float v0 = e[lane];
    float v1 = (lane < 8) ? e[lane + 32] : -3.4e38f;
    float m = fmaxf(v0, v1);
    #pragma unroll
    for (int o = 16; o > 0; o >>= 1) m = fmaxf(m, __shfl_xor_sync(0xffffffffu, m, o));
    float s = expf(v0 - m) + ((lane < 8) ? expf(v1 - m) : 0.f);
    #pragma unroll
    for (int o = 16; o > 0; o >>= 1) s += __shfl_xor_sync(0xffffffffu, s, o);
    float lse = m + logf(s);
    out[(size_t)wid * 40 + lane] = v0 - lse;
    if (lane < 8) out[(size_t)wid * 40 + lane + 32] = v1 - lse;
}

// ---------------- launcher ----------------
extern "C" void kernel_launch(void* const* d_in, const int* in_sizes, int n_in,
                              void* d_out, int out_size) {
    const float* x   = (const float*)d_in[0];
    const void*  ei  = d_in[1];                 // int32 or int64, detected on device
    const float* W1  = (const float*)d_in[2];
    const float* b1  = (const float*)d_in[3];
    const float* W2  = (const float*)d_in[4];
    const float* b2  = (const float*)d_in[5];
    const float* W3  = (const float*)d_in[6];
    const float* b3  = (const float*)d_in[7];
    const float* g1  = (const float*)d_in[8];
    const float* be1 = (const float*)d_in[9];
    const float* g2  = (const float*)d_in[10];
    const float* be2 = (const float*)d_in[11];
    float* out = (float*)d_out;

    float *hP, *aP, *W2fP, *W3fP, *t2P, *t3P, *z64P, *s1P, *s2P;
    cudaGetSymbolAddress((void**)&hP,   g_h);
    cudaGetSymbolAddress((void**)&aP,   g_agg);
    cudaGetSymbolAddress((void**)&W2fP, g_W2f);
    cudaGetSymbolAddress((void**)&W3fP, g_W3f);
    cudaGetSymbolAddress((void**)&t2P,  g_t2);
    cudaGetSymbolAddress((void**)&t3P,  g_t3);
    cudaGetSymbolAddress((void**)&z64P, g_zero64);
    cudaGetSymbolAddress((void**)&s1P,  g_stats1);
    cudaGetSymbolAddress((void**)&s2P,  g_stats2);

    // output layout: (out, emb) concatenated
    float* emb = (out_size >= 2 * NN * 40) ? (out + NN * 40) : aP;

    // graph build
    k_init  <<<(NN + 255) / 256, 256>>>();
    k_detect<<<(EE + 255) / 256, 256>>>((const long long*)ei);
    k_degree<<<(EE + 255) / 256, 256>>>(ei);
    k_dinv  <<<(NN + 255) / 256, 256>>>();
    k_scanA <<<NB, 256>>>();
    k_scanB <<<1, 32>>>();
    k_scanC <<<NB, 256>>>();
    k_fill  <<<(MM + 255) / 256, 256>>>(ei);
    k_rowsum<<<(NN + 7) / 8, 256>>>();

    // layer 1
    k_gemm<64><<<(NN + 63) / 64, 256>>>(x, W1, hP);
    k_agg<64> <<<(NN + 7) / 8, 256>>>(hP, b1, z64P, aP);
    k_stats   <<<256, 256>>>(aP, s1P);
    k_fold<64><<<1, 256>>>(W2, g1, be1, s1P, W2fP, t2P);

    // layer 2 (BN1 folded into W2)
    k_gemm<64><<<(NN + 63) / 64, 256>>>(aP, W2fP, hP);
    k_agg<64> <<<(NN + 7) / 8, 256>>>(hP, b2, t2P, aP);
    k_stats   <<<256, 256>>>(aP, s2P);
    k_fold<40><<<1, 256>>>(W3, g2, be2, s2P, W3fP, t3P);

    // layer 3 (BN2 folded into W3) -> emb, then log_softmax -> out
    k_gemm<40><<<(NN + 63) / 64, 160>>>(aP, W3fP, hP);
    k_agg<40> <<<(NN + 7) / 8, 256>>>(hP, b3, t3P, emb);
    k_lsm     <<<(NN + 7) / 8, 256>>>(emb, out);
}